// round 16
// baseline (speedup 1.0000x reference)
#include <cuda_runtime.h>
#include <cuda_fp16.h>
#include <math.h>
#include <stdint.h>

#define T_TOK 4096
#define HDIM  1024
#define IDIM  2816
#define NE    7
#define BK    32

// smem row pitch: 40 halves = 80 bytes -> conflict-free ldmatrix with 8-row strides
#define PITCHB 80

// per-stage layout (bytes): A 128 rows, B 256 rows
#define S_B   10240
#define STAGE 30720
#define NST   4
#define SM_G1 (NST*STAGE + 512)
#define SM_G2 (NST*STAGE)

// ---------------- device scratch ----------------
__device__ __half g_xh[(size_t)T_TOK*HDIM];     // x fp16
__device__ __half g_g1h[8ull*IDIM*HDIM];   // gate weights [z][n][k], fp16
__device__ __half g_u1h[8ull*IDIM*HDIM];   // up weights
__device__ __half g_d2h[8ull*HDIM*IDIM];   // down weights [z][n][k]
__device__ __half g_y1h[8ull*T_TOK*IDIM];  // y1 fp16
__device__ float g_y2[(size_t)NE*T_TOK*HDIM];  // routed expert outputs (compacted rows)
__device__ int   g_cnt[NE];
__device__ int   g_tok[NE * T_TOK];
__device__ int   g_srow[2 * T_TOK];        // per token: compacted global row per slot
__device__ float g_swt [2 * T_TOK];        // per token: renormalized weight per slot

// ---------------- helpers ----------------
__device__ __forceinline__ uint32_t smem_u32(const void* p) {
    uint32_t a;
    asm("{ .reg .u64 t; cvta.to.shared.u64 t, %1; cvt.u32.u64 %0, t; }" : "=r"(a) : "l"(p));
    return a;
}
__device__ __forceinline__ void ldmx4(uint32_t* r, uint32_t addr) {
    asm volatile("ldmatrix.sync.aligned.m8n8.x4.shared.b16 {%0,%1,%2,%3}, [%4];"
        : "=r"(r[0]), "=r"(r[1]), "=r"(r[2]), "=r"(r[3]) : "r"(addr));
}
__device__ __forceinline__ void mma16816(float* d, const uint32_t* a, const uint32_t* b) {
    asm volatile("mma.sync.aligned.m16n8k16.row.col.f32.f16.f16.f32 "
        "{%0,%1,%2,%3}, {%4,%5,%6,%7}, {%8,%9}, {%0,%1,%2,%3};"
        : "+f"(d[0]), "+f"(d[1]), "+f"(d[2]), "+f"(d[3])
        : "r"(a[0]), "r"(a[1]), "r"(a[2]), "r"(a[3]), "r"(b[0]), "r"(b[1]));
}
__device__ __forceinline__ void cp16(uint32_t saddr, const void* gaddr) {
    asm volatile("cp.async.cg.shared.global [%0], [%1], 16;" :: "r"(saddr), "l"(gaddr));
}
__device__ __forceinline__ void cp_commit() { asm volatile("cp.async.commit_group;" ::: "memory"); }
template<int N> __device__ __forceinline__ void cp_wait() {
    asm volatile("cp.async.wait_group %0;" :: "n"(N) : "memory");
}

// ---------------- small kernels ----------------
__global__ void init_counts_kernel() {
    if (threadIdx.x < NE) g_cnt[threadIdx.x] = 0;
}

__global__ void router_kernel(const float* __restrict__ x,
                              const float* __restrict__ wr,
                              const float* __restrict__ bias) {
    int warp = (blockIdx.x * blockDim.x + threadIdx.x) >> 5;
    int lane = threadIdx.x & 31;
    if (warp >= T_TOK) return;
    const float* xr = x + (size_t)warp * HDIM;
    float acc[NE];
#pragma unroll
    for (int e = 0; e < NE; e++) acc[e] = 0.f;
    for (int h = lane; h < HDIM; h += 32) {
        float xv = xr[h];
#pragma unroll
        for (int e = 0; e < NE; e++) acc[e] += xv * wr[h * NE + e];
    }
#pragma unroll
    for (int e = 0; e < NE; e++) {
#pragma unroll
        for (int o = 16; o > 0; o >>= 1)
            acc[e] += __shfl_xor_sync(0xffffffffu, acc[e], o);
    }
    if (lane == 0) {
        float p[NE];
#pragma unroll
        for (int e = 0; e < NE; e++)
            p[e] = 1.f / (1.f + expf(-(acc[e] + bias[e])));
        int i0 = 0; float s0 = p[0];
#pragma unroll
        for (int e = 1; e < NE; e++) if (p[e] > s0) { s0 = p[e]; i0 = e; }
        int i1 = -1; float s1 = -1.f;
#pragma unroll
        for (int e = 0; e < NE; e++) if (e != i0 && p[e] > s1) { s1 = p[e]; i1 = e; }
        float inv = 1.f / (s0 + s1);
        int p0 = atomicAdd(&g_cnt[i0], 1);
        g_tok[i0 * T_TOK + p0] = warp;
        g_srow[2 * warp]     = i0 * T_TOK + p0;
        g_swt [2 * warp]     = s0 * inv;
        int p1 = atomicAdd(&g_cnt[i1], 1);
        g_tok[i1 * T_TOK + p1] = warp;
        g_srow[2 * warp + 1] = i1 * T_TOK + p1;
        g_swt [2 * warp + 1] = s1 * inv;
    }
}

// x -> fp16
__global__ void convx_kernel(const float* __restrict__ x) {
    size_t i = ((size_t)blockIdx.x * 256 + threadIdx.x) * 4;
    float4 v = *(const float4*)(x + i);
    __half h[4];
    h[0] = __float2half_rn(v.x); h[1] = __float2half_rn(v.y);
    h[2] = __float2half_rn(v.z); h[3] = __float2half_rn(v.w);
    *(uint2*)(g_xh + i) = *(uint2*)h;
}

// transpose-convert: src fp32 [K][N] row-major -> dst fp16 [N][K]
// tile 32k x 64n, 256 threads, float4 loads / uint2 (4xhalf) stores
__device__ __forceinline__ void transpose_cv2(const float* __restrict__ src,
                                              __half* dh, int K, int N) {
    __shared__ float t[64][33];
    int tid = threadIdx.x;
    int n0 = blockIdx.x * 64, k0 = blockIdx.y * 32;
#pragma unroll
    for (int i = 0; i < 2; i++) {
        int r  = (tid >> 4) + i * 16;      // 0..31  (k within tile)
        int c4 = (tid & 15) * 4;           // 0..60  (n within tile)
        float4 v = *(const float4*)(src + (size_t)(k0 + r) * N + n0 + c4);
        t[c4 + 0][r] = v.x; t[c4 + 1][r] = v.y;
        t[c4 + 2][r] = v.z; t[c4 + 3][r] = v.w;
    }
    __syncthreads();
#pragma unroll
    for (int i = 0; i < 2; i++) {
        int n  = (tid >> 3) + i * 32;      // 0..63
        int kc = (tid & 7) * 4;            // 0..28
        __half h[4];
        h[0] = __float2half_rn(t[n][kc + 0]);
        h[1] = __float2half_rn(t[n][kc + 1]);
        h[2] = __float2half_rn(t[n][kc + 2]);
        h[3] = __float2half_rn(t[n][kc + 3]);
        *(uint2*)(dh + (size_t)(n0 + n) * K + k0 + kc) = *(uint2*)h;
    }
}

__global__ void convT1_kernel(const float* __restrict__ sg, const float* __restrict__ su,
                              const float* __restrict__ rg, const float* __restrict__ ru) {
    int z = blockIdx.z;
    const float* src; __half* dh; size_t mo;
    if (z == 0)       { src = sg; dh = g_g1h; mo = 0; }
    else if (z == 1)  { src = su; dh = g_u1h; mo = 0; }
    else if (z < 9)   { int e = z - 2; src = rg + (size_t)e * HDIM * IDIM; dh = g_g1h; mo = (size_t)(e + 1) * IDIM * HDIM; }
    else              { int e = z - 9; src = ru + (size_t)e * HDIM * IDIM; dh = g_u1h; mo = (size_t)(e + 1) * IDIM * HDIM; }
    transpose_cv2(src, dh + mo, HDIM, IDIM);
}

__global__ void convT2_kernel(const float* __restrict__ sd, const float* __restrict__ rd) {
    int z = blockIdx.z;
    const float* src = (z == 0) ? sd : rd + (size_t)(z - 1) * IDIM * HDIM;
    transpose_cv2(src, g_d2h + (size_t)z * HDIM * IDIM, IDIM, HDIM);
}

// ---------------- gemm1: y1 = silu(x@G) * (x@U)  (pure fp16 operands, fp32 accum) ----------------
// CTA tile: 128 m x 128 n (gate AND up).  8 warps 2m x 4n, warp tile 64m x 32n (x2 paths).
__global__ __launch_bounds__(256, 1)
void gemm1_kernel() {
    extern __shared__ char smem[];
    int tid = threadIdx.x;
    int z = blockIdx.z;
    int nrows; const int* idx;
    if (z == 0) { nrows = T_TOK; idx = nullptr; }
    else        { nrows = g_cnt[z - 1]; idx = g_tok + (z - 1) * T_TOK; }
    int m0 = blockIdx.y * 128;
    if (m0 >= nrows) return;
    int n0 = blockIdx.x * 128;

    const __half* gH = g_g1h + (size_t)z * IDIM * HDIM;
    const __half* uH = g_u1h + (size_t)z * IDIM * HDIM;

    int* arow_s = (int*)(smem + NST * STAGE);
    if (tid < 128) {
        int gm = m0 + tid;
        arow_s[tid] = idx ? ((gm < nrows) ? idx[gm] : idx[0]) : gm;
    }
    __syncthreads();
    uint32_t sb = smem_u32(smem);

    // stage: A 128 rows, B 256 rows (gate 0-127 = n0..n0+127, up 128-255)
    auto load_stage = [&](int s, int k0) {
        uint32_t base = sb + s * STAGE;
#pragma unroll
        for (int i = 0; i < 6; i++) {
            int cid = tid + i * 256;       // 0..1535
            const __half* src;
            uint32_t dst;
            if (cid < 512) {
                int row = cid >> 2, c = cid & 3;
                src = g_xh + (size_t)arow_s[row] * HDIM + k0 + c * 8;
                dst = base + row * PITCHB + c * 16;
            } else {
                int w2 = cid - 512;        // 0..1023
                int row = w2 >> 2, c = w2 & 3;
                const __half* bp;
                if (row < 128) bp = gH + (size_t)(n0 + row) * HDIM;
                else           bp = uH + (size_t)(n0 + row - 128) * HDIM;
                src = bp + k0 + c * 8;
                dst = base + S_B + row * PITCHB + c * 16;
            }
            cp16(dst, src);
        }
    };

    int l = tid & 31, w = tid >> 5;
    int wm = w & 1, wn = w >> 1;         // warp grid 2m x 4n
    int mW = wm * 64, nW = wn * 32;
    uint32_t aRow = (uint32_t)(l & 15);
    uint32_t aKb  = (uint32_t)(((l >> 4) & 1) * 16);
    uint32_t bRow = (uint32_t)((l & 7) + ((l >> 4) & 1) * 8);
    uint32_t bKb  = (uint32_t)(((l >> 3) & 1) * 16);

    float Cg[4][4][4] = {}, Cu[4][4][4] = {};

    for (int s = 0; s < NST - 1; s++) { load_stage(s, s * BK); cp_commit(); }
    const int NIT = HDIM / BK;   // 32
    for (int it = 0; it < NIT; it++) {
        cp_wait<NST - 2>();
        __syncthreads();
        // issue prefetch for stage it+NST-1 BEFORE compute so it overlaps the MMAs
        int nl = it + NST - 1;
        if (nl < NIT) load_stage(nl % NST, nl * BK);
        cp_commit();
        uint32_t base = sb + (it % NST) * STAGE;
#pragma unroll
        for (int ks = 0; ks < 2; ks++) {
            int kb = ks * 32;   // bytes (16 elts * 2B)
            uint32_t ah[4][4];
#pragma unroll
            for (int mt = 0; mt < 4; mt++) {
                uint32_t r = base + (mW + mt * 16 + aRow) * PITCHB + kb + aKb;
                ldmx4(ah[mt], r);
            }
            uint32_t bg[2][4], bu[2][4];
#pragma unroll
            for (int p = 0; p < 2; p++) {
                uint32_t rg2 = base + S_B + (nW + p * 16 + bRow) * PITCHB + kb + bKb;
                ldmx4(bg[p], rg2);
                ldmx4(bu[p], rg2 + 128 * PITCHB);
            }
#pragma unroll
            for (int mt = 0; mt < 4; mt++)
#pragma unroll
                for (int nt = 0; nt < 4; nt++) {
                    const uint32_t* bG = &bg[nt >> 1][(nt & 1) * 2];
                    const uint32_t* bU = &bu[nt >> 1][(nt & 1) * 2];
                    mma16816(Cg[mt][nt], ah[mt], bG);
                    mma16816(Cu[mt][nt], ah[mt], bU);
                }
        }
    }

    // epilogue: y = silu(g)*u -> fp16, compacted rows
    size_t zb = (size_t)z * T_TOK;
#pragma unroll
    for (int mt = 0; mt < 4; mt++)
#pragma unroll
        for (int nt = 0; nt < 4; nt++) {
            int mrow = m0 + mW + mt * 16 + (l >> 2);
            int ncol = n0 + nW + nt * 8 + (l & 3) * 2;
#pragma unroll
            for (int h = 0; h < 2; h++) {
                int m = mrow + h * 8;
                if (m < nrows) {
                    float gg0 = Cg[mt][nt][2 * h],     uu0 = Cu[mt][nt][2 * h];
                    float gg1 = Cg[mt][nt][2 * h + 1], uu1 = Cu[mt][nt][2 * h + 1];
                    float y0 = gg0 / (1.f + __expf(-gg0)) * uu0;
                    float y1 = gg1 / (1.f + __expf(-gg1)) * uu1;
                    __half2 t2 = __floats2half2_rn(y0, y1);
                    *(uint32_t*)(g_y1h + (zb + m) * IDIM + ncol) = *(uint32_t*)&t2;
                }
            }
        }
}

// ---------------- gemm2: out = y1 @ D  (pure fp16 operands) ----------------
// CTA tile: 128 m x 256 n.  8 warps 2m x 4n, warp tile 64m x 64n.
// z = 0: shared expert -> direct store to out.  z >= 1: routed -> g_y2 scratch rows.
__global__ __launch_bounds__(256, 1)
void gemm2_kernel(float* __restrict__ out) {
    extern __shared__ char smem[];
    int tid = threadIdx.x;
    int z = blockIdx.z;
    int nrows = z ? g_cnt[z - 1] : T_TOK;
    int m0 = blockIdx.y * 128;
    if (m0 >= nrows) return;
    int n0 = blockIdx.x * 256;

    const __half* aH = g_y1h + (size_t)z * T_TOK * IDIM;
    const __half* bH = g_d2h + (size_t)z * HDIM * IDIM;

    uint32_t sb = smem_u32(smem);

    auto load_stage = [&](int s, int k0) {
        uint32_t base = sb + s * STAGE;
#pragma unroll
        for (int i = 0; i < 6; i++) {
            int cid = tid + i * 256;
            const __half* src;
            uint32_t dst;
            if (cid < 512) {
                int row = cid >> 2, c = cid & 3;
                int r = m0 + row; if (r >= nrows) r = nrows - 1;
                src = aH + (size_t)r * IDIM + k0 + c * 8;
                dst = base + row * PITCHB + c * 16;
            } else {
                int w2 = cid - 512;
                int row = w2 >> 2, c = w2 & 3;
                src = bH + (size_t)(n0 + row) * IDIM + k0 + c * 8;
                dst = base + S_B + row * PITCHB + c * 16;
            }
            cp16(dst, src);
        }
    };

    int l = tid & 31, w = tid >> 5;
    int wm = w & 1, wn = w >> 1;         // warp grid 2m x 4n
    int mW = wm * 64, nW = wn * 64;
    uint32_t aRow = (uint32_t)(l & 15);
    uint32_t aKb  = (uint32_t)(((l >> 4) & 1) * 16);
    uint32_t bRow = (uint32_t)((l & 7) + ((l >> 4) & 1) * 8);
    uint32_t bKb  = (uint32_t)(((l >> 3) & 1) * 16);

    float C[4][8][4] = {};

    for (int s = 0; s < NST - 1; s++) { load_stage(s, s * BK); cp_commit(); }
    const int NIT = IDIM / BK;   // 88
    for (int it = 0; it < NIT; it++) {
        cp_wait<NST - 2>();
        __syncthreads();
        int nl = it + NST - 1;
        if (nl < NIT) load_stage(nl % NST, nl * BK);
        cp_commit();
        uint32_t base = sb + (it % NST) * STAGE;
#pragma unroll
        for (int ks = 0; ks < 2; ks++) {
            int kb = ks * 32;
            uint32_t ah[4][4];
#pragma unroll
            for (int mt = 0; mt < 4; mt++) {
                uint32_t r = base + (mW + mt * 16 + aRow) * PITCHB + kb + aKb;
                ldmx4(ah[mt], r);
            }
            uint32_t bh[4][4];
#pragma unroll
            for (int p = 0; p < 4; p++) {
                uint32_t r = base + S_B + (nW + p * 16 + bRow) * PITCHB + kb + bKb;
                ldmx4(bh[p], r);
            }
#pragma unroll
            for (int mt = 0; mt < 4; mt++)
#pragma unroll
                for (int nt = 0; nt < 8; nt++) {
                    const uint32_t* bF = &bh[nt >> 1][(nt & 1) * 2];
                    mma16816(C[mt][nt], ah[mt], bF);
                }
        }
    }

    float* dstbase = z ? (g_y2 + (size_t)(z - 1) * T_TOK * HDIM) : out;
#pragma unroll
    for (int mt = 0; mt < 4; mt++)
#pragma unroll
        for (int nt = 0; nt < 8; nt++) {
            int mrow = m0 + mW + mt * 16 + (l >> 2);
            int ncol = n0 + nW + nt * 8 + (l & 3) * 2;
#pragma unroll
            for (int h = 0; h < 2; h++) {
                int m = mrow + h * 8;
                if (m < nrows) {
                    float2 v = make_float2(C[mt][nt][2 * h], C[mt][nt][2 * h + 1]);
                    *(float2*)(dstbase + (size_t)m * HDIM + ncol) = v;
                }
            }
        }
}

// ---------------- combine: out[t] += w0*y2[row0] + w1*y2[row1] ----------------
__global__ void combine_kernel(float* __restrict__ out) {
    int t = blockIdx.x;
    int h = threadIdx.x * 4;
    int r0 = g_srow[2 * t],  r1 = g_srow[2 * t + 1];
    float w0 = g_swt[2 * t], w1 = g_swt[2 * t + 1];
    float4 o = *(float4*)(out + (size_t)t * HDIM + h);
    float4 a = *(const float4*)(g_y2 + (size_t)r0 * HDIM + h);
    float4 b = *(const float4*)(g_y2 + (size_t)r1 * HDIM + h);
    o.x += w0 * a.x + w1 * b.x;
    o.y += w0 * a.y + w1 * b.y;
    o.z += w0 * a.z + w1 * b.z;
    o.w += w0 * a.w + w1 * b.w;
    *(float4*)(out + (size_t)t * HDIM + h) = o;
}

// ---------------- launch ----------------
extern "C" void kernel_launch(void* const* d_in, const int* in_sizes, int n_in,
                              void* d_out, int out_size) {
    const float* x    = (const float*)d_in[0];
    const float* wr   = (const float*)d_in[1];
    const float* bias = (const float*)d_in[2];
    const float* sg   = (const float*)d_in[3];
    const float* su   = (const float*)d_in[4];
    const float* sd   = (const float*)d_in[5];
    const float* rg   = (const float*)d_in[6];
    const float* ru   = (const float*)d_in[7];
    const float* rd   = (const float*)d_in[8];
    float* out = (float*)d_out;

    cudaFuncSetAttribute(gemm1_kernel, cudaFuncAttributeMaxDynamicSharedMemorySize, SM_G1);
    cudaFuncSetAttribute(gemm2_kernel, cudaFuncAttributeMaxDynamicSharedMemorySize, SM_G2);

    init_counts_kernel<<<1, 32>>>();
    router_kernel<<<T_TOK / 4, 128>>>(x, wr, bias);
    convx_kernel<<<(T_TOK * HDIM) / 1024, 256>>>(x);
    convT1_kernel<<<dim3(IDIM / 64, HDIM / 32, 16), 256>>>(sg, su, rg, ru);
    convT2_kernel<<<dim3(HDIM / 64, IDIM / 32, 8), 256>>>(sd, rd);

    gemm1_kernel<<<dim3(IDIM / 128, T_TOK / 128, 8), 256, SM_G1>>>();
    gemm2_kernel<<<dim3(HDIM / 256, T_TOK / 128, 8), 256, SM_G2>>>(out);
    combine_kernel<<<T_TOK, HDIM / 4>>>(out);
}

// round 17
// speedup vs baseline: 1.1373x; 1.1373x over previous
#include <cuda_runtime.h>
#include <cuda_fp16.h>
#include <math.h>
#include <stdint.h>

#define T_TOK 4096
#define HDIM  1024
#define IDIM  2816
#define NE    7
#define BK    32

// smem row pitch: 40 halves = 80 bytes -> conflict-free ldmatrix with 8-row strides
#define PITCHB 80

// per-stage layout (bytes): A 128 rows, B 256 rows
#define S_B   10240
#define STAGE 30720
#define NST   4
#define SM_G1 (NST*STAGE + 512)
#define SM_G2 (NST*STAGE)

// ---------------- device scratch ----------------
__device__ __half g_xh[(size_t)T_TOK*HDIM];     // x fp16
__device__ __half g_g1h[8ull*IDIM*HDIM];   // gate weights [z][n][k], fp16
__device__ __half g_u1h[8ull*IDIM*HDIM];   // up weights
__device__ __half g_d2h[8ull*HDIM*IDIM];   // down weights [z][n][k]
__device__ __half g_y1h[8ull*T_TOK*IDIM];  // y1 fp16
__device__ float g_y2[(size_t)NE*T_TOK*HDIM];  // routed expert outputs (compacted rows)
__device__ int   g_cnt[NE];
__device__ int   g_tok[NE * T_TOK];
__device__ int   g_srow[2 * T_TOK];        // per token: compacted global row per slot
__device__ float g_swt [2 * T_TOK];        // per token: renormalized weight per slot

// ---------------- helpers ----------------
__device__ __forceinline__ uint32_t smem_u32(const void* p) {
    uint32_t a;
    asm("{ .reg .u64 t; cvta.to.shared.u64 t, %1; cvt.u32.u64 %0, t; }" : "=r"(a) : "l"(p));
    return a;
}
__device__ __forceinline__ void ldmx4(uint32_t* r, uint32_t addr) {
    asm volatile("ldmatrix.sync.aligned.m8n8.x4.shared.b16 {%0,%1,%2,%3}, [%4];"
        : "=r"(r[0]), "=r"(r[1]), "=r"(r[2]), "=r"(r[3]) : "r"(addr));
}
__device__ __forceinline__ void mma16816(float* d, const uint32_t* a, const uint32_t* b) {
    asm volatile("mma.sync.aligned.m16n8k16.row.col.f32.f16.f16.f32 "
        "{%0,%1,%2,%3}, {%4,%5,%6,%7}, {%8,%9}, {%0,%1,%2,%3};"
        : "+f"(d[0]), "+f"(d[1]), "+f"(d[2]), "+f"(d[3])
        : "r"(a[0]), "r"(a[1]), "r"(a[2]), "r"(a[3]), "r"(b[0]), "r"(b[1]));
}
__device__ __forceinline__ void cp16(uint32_t saddr, const void* gaddr) {
    asm volatile("cp.async.cg.shared.global [%0], [%1], 16;" :: "r"(saddr), "l"(gaddr));
}
__device__ __forceinline__ void cp_commit() { asm volatile("cp.async.commit_group;" ::: "memory"); }
template<int N> __device__ __forceinline__ void cp_wait() {
    asm volatile("cp.async.wait_group %0;" :: "n"(N) : "memory");
}

// ---------------- small kernels ----------------
__global__ void init_counts_kernel() {
    if (threadIdx.x < NE) g_cnt[threadIdx.x] = 0;
}

__global__ void router_kernel(const float* __restrict__ x,
                              const float* __restrict__ wr,
                              const float* __restrict__ bias) {
    int warp = (blockIdx.x * blockDim.x + threadIdx.x) >> 5;
    int lane = threadIdx.x & 31;
    if (warp >= T_TOK) return;
    const float* xr = x + (size_t)warp * HDIM;
    float acc[NE];
#pragma unroll
    for (int e = 0; e < NE; e++) acc[e] = 0.f;
    for (int h = lane; h < HDIM; h += 32) {
        float xv = xr[h];
#pragma unroll
        for (int e = 0; e < NE; e++) acc[e] += xv * wr[h * NE + e];
    }
#pragma unroll
    for (int e = 0; e < NE; e++) {
#pragma unroll
        for (int o = 16; o > 0; o >>= 1)
            acc[e] += __shfl_xor_sync(0xffffffffu, acc[e], o);
    }
    if (lane == 0) {
        float p[NE];
#pragma unroll
        for (int e = 0; e < NE; e++)
            p[e] = 1.f / (1.f + expf(-(acc[e] + bias[e])));
        int i0 = 0; float s0 = p[0];
#pragma unroll
        for (int e = 1; e < NE; e++) if (p[e] > s0) { s0 = p[e]; i0 = e; }
        int i1 = -1; float s1 = -1.f;
#pragma unroll
        for (int e = 0; e < NE; e++) if (e != i0 && p[e] > s1) { s1 = p[e]; i1 = e; }
        float inv = 1.f / (s0 + s1);
        int p0 = atomicAdd(&g_cnt[i0], 1);
        g_tok[i0 * T_TOK + p0] = warp;
        g_srow[2 * warp]     = i0 * T_TOK + p0;
        g_swt [2 * warp]     = s0 * inv;
        int p1 = atomicAdd(&g_cnt[i1], 1);
        g_tok[i1 * T_TOK + p1] = warp;
        g_srow[2 * warp + 1] = i1 * T_TOK + p1;
        g_swt [2 * warp + 1] = s1 * inv;
    }
}

// x -> fp16
__global__ void convx_kernel(const float* __restrict__ x) {
    size_t i = ((size_t)blockIdx.x * 256 + threadIdx.x) * 4;
    float4 v = *(const float4*)(x + i);
    __half h[4];
    h[0] = __float2half_rn(v.x); h[1] = __float2half_rn(v.y);
    h[2] = __float2half_rn(v.z); h[3] = __float2half_rn(v.w);
    *(uint2*)(g_xh + i) = *(uint2*)h;
}

// transpose-convert: src fp32 [K][N] row-major -> dst fp16 [N][K]
// tile 32k x 64n, 256 threads, float4 loads / uint2 (4xhalf) stores
__device__ __forceinline__ void transpose_cv2(const float* __restrict__ src,
                                              __half* dh, int K, int N) {
    __shared__ float t[64][33];
    int tid = threadIdx.x;
    int n0 = blockIdx.x * 64, k0 = blockIdx.y * 32;
#pragma unroll
    for (int i = 0; i < 2; i++) {
        int r  = (tid >> 4) + i * 16;      // 0..31  (k within tile)
        int c4 = (tid & 15) * 4;           // 0..60  (n within tile)
        float4 v = *(const float4*)(src + (size_t)(k0 + r) * N + n0 + c4);
        t[c4 + 0][r] = v.x; t[c4 + 1][r] = v.y;
        t[c4 + 2][r] = v.z; t[c4 + 3][r] = v.w;
    }
    __syncthreads();
#pragma unroll
    for (int i = 0; i < 2; i++) {
        int n  = (tid >> 3) + i * 32;      // 0..63
        int kc = (tid & 7) * 4;            // 0..28
        __half h[4];
        h[0] = __float2half_rn(t[n][kc + 0]);
        h[1] = __float2half_rn(t[n][kc + 1]);
        h[2] = __float2half_rn(t[n][kc + 2]);
        h[3] = __float2half_rn(t[n][kc + 3]);
        *(uint2*)(dh + (size_t)(n0 + n) * K + k0 + kc) = *(uint2*)h;
    }
}

__global__ void convT1_kernel(const float* __restrict__ sg, const float* __restrict__ su,
                              const float* __restrict__ rg, const float* __restrict__ ru) {
    int z = blockIdx.z;
    const float* src; __half* dh; size_t mo;
    if (z == 0)       { src = sg; dh = g_g1h; mo = 0; }
    else if (z == 1)  { src = su; dh = g_u1h; mo = 0; }
    else if (z < 9)   { int e = z - 2; src = rg + (size_t)e * HDIM * IDIM; dh = g_g1h; mo = (size_t)(e + 1) * IDIM * HDIM; }
    else              { int e = z - 9; src = ru + (size_t)e * HDIM * IDIM; dh = g_u1h; mo = (size_t)(e + 1) * IDIM * HDIM; }
    transpose_cv2(src, dh + mo, HDIM, IDIM);
}

__global__ void convT2_kernel(const float* __restrict__ sd, const float* __restrict__ rd) {
    int z = blockIdx.z;
    const float* src = (z == 0) ? sd : rd + (size_t)(z - 1) * IDIM * HDIM;
    transpose_cv2(src, g_d2h + (size_t)z * HDIM * IDIM, IDIM, HDIM);
}

// ---------------- gemm1: y1 = silu(x@G) * (x@U)  (pure fp16 operands, fp32 accum) ----------------
// CTA tile: 128 m x 128 n (gate AND up).  8 warps 2m x 4n, warp tile 64m x 32n (x2 paths).
__global__ __launch_bounds__(256, 1)
void gemm1_kernel() {
    extern __shared__ char smem[];
    int tid = threadIdx.x;
    int z = blockIdx.z;
    int nrows; const int* idx;
    if (z == 0) { nrows = T_TOK; idx = nullptr; }
    else        { nrows = g_cnt[z - 1]; idx = g_tok + (z - 1) * T_TOK; }
    int m0 = blockIdx.y * 128;
    if (m0 >= nrows) return;
    int n0 = blockIdx.x * 128;

    const __half* gH = g_g1h + (size_t)z * IDIM * HDIM;
    const __half* uH = g_u1h + (size_t)z * IDIM * HDIM;

    int* arow_s = (int*)(smem + NST * STAGE);
    if (tid < 128) {
        int gm = m0 + tid;
        arow_s[tid] = idx ? ((gm < nrows) ? idx[gm] : idx[0]) : gm;
    }
    __syncthreads();
    uint32_t sb = smem_u32(smem);

    // stage: A 128 rows, B 256 rows (gate 0-127 = n0..n0+127, up 128-255)
    auto load_stage = [&](int s, int k0) {
        uint32_t base = sb + s * STAGE;
#pragma unroll
        for (int i = 0; i < 6; i++) {
            int cid = tid + i * 256;       // 0..1535
            const __half* src;
            uint32_t dst;
            if (cid < 512) {
                int row = cid >> 2, c = cid & 3;
                src = g_xh + (size_t)arow_s[row] * HDIM + k0 + c * 8;
                dst = base + row * PITCHB + c * 16;
            } else {
                int w2 = cid - 512;        // 0..1023
                int row = w2 >> 2, c = w2 & 3;
                const __half* bp;
                if (row < 128) bp = gH + (size_t)(n0 + row) * HDIM;
                else           bp = uH + (size_t)(n0 + row - 128) * HDIM;
                src = bp + k0 + c * 8;
                dst = base + S_B + row * PITCHB + c * 16;
            }
            cp16(dst, src);
        }
    };

    int l = tid & 31, w = tid >> 5;
    int wm = w & 1, wn = w >> 1;         // warp grid 2m x 4n
    int mW = wm * 64, nW = wn * 32;
    uint32_t aRow = (uint32_t)(l & 15);
    uint32_t aKb  = (uint32_t)(((l >> 4) & 1) * 16);
    uint32_t bRow = (uint32_t)((l & 7) + ((l >> 4) & 1) * 8);
    uint32_t bKb  = (uint32_t)(((l >> 3) & 1) * 16);

    float Cg[4][4][4] = {}, Cu[4][4][4] = {};

    for (int s = 0; s < NST - 1; s++) { load_stage(s, s * BK); cp_commit(); }
    const int NIT = HDIM / BK;   // 32
    for (int it = 0; it < NIT; it++) {
        cp_wait<NST - 2>();
        __syncthreads();
        uint32_t base = sb + (it % NST) * STAGE;
#pragma unroll
        for (int ks = 0; ks < 2; ks++) {
            int kb = ks * 32;   // bytes (16 elts * 2B)
            uint32_t ah[4][4];
#pragma unroll
            for (int mt = 0; mt < 4; mt++) {
                uint32_t r = base + (mW + mt * 16 + aRow) * PITCHB + kb + aKb;
                ldmx4(ah[mt], r);
            }
            uint32_t bg[2][4], bu[2][4];
#pragma unroll
            for (int p = 0; p < 2; p++) {
                uint32_t rg2 = base + S_B + (nW + p * 16 + bRow) * PITCHB + kb + bKb;
                ldmx4(bg[p], rg2);
                ldmx4(bu[p], rg2 + 128 * PITCHB);
            }
#pragma unroll
            for (int mt = 0; mt < 4; mt++)
#pragma unroll
                for (int nt = 0; nt < 4; nt++) {
                    const uint32_t* bG = &bg[nt >> 1][(nt & 1) * 2];
                    const uint32_t* bU = &bu[nt >> 1][(nt & 1) * 2];
                    mma16816(Cg[mt][nt], ah[mt], bG);
                    mma16816(Cu[mt][nt], ah[mt], bU);
                }
        }
        int nl = it + NST - 1;
        if (nl < NIT) load_stage(nl % NST, nl * BK);
        cp_commit();
    }

    // epilogue: y = silu(g)*u -> fp16, compacted rows
    size_t zb = (size_t)z * T_TOK;
#pragma unroll
    for (int mt = 0; mt < 4; mt++)
#pragma unroll
        for (int nt = 0; nt < 4; nt++) {
            int mrow = m0 + mW + mt * 16 + (l >> 2);
            int ncol = n0 + nW + nt * 8 + (l & 3) * 2;
#pragma unroll
            for (int h = 0; h < 2; h++) {
                int m = mrow + h * 8;
                if (m < nrows) {
                    float gg0 = Cg[mt][nt][2 * h],     uu0 = Cu[mt][nt][2 * h];
                    float gg1 = Cg[mt][nt][2 * h + 1], uu1 = Cu[mt][nt][2 * h + 1];
                    float y0 = gg0 / (1.f + __expf(-gg0)) * uu0;
                    float y1 = gg1 / (1.f + __expf(-gg1)) * uu1;
                    __half2 t2 = __floats2half2_rn(y0, y1);
                    *(uint32_t*)(g_y1h + (zb + m) * IDIM + ncol) = *(uint32_t*)&t2;
                }
            }
        }
}

// ---------------- gemm2: out = y1 @ D  (pure fp16 operands) ----------------
// CTA tile: 128 m x 256 n.  8 warps 2m x 4n, warp tile 64m x 64n.
// z = 0: shared expert -> direct store to out.  z >= 1: routed -> g_y2 scratch rows.
__global__ __launch_bounds__(256, 1)
void gemm2_kernel(float* __restrict__ out) {
    extern __shared__ char smem[];
    int tid = threadIdx.x;
    int z = blockIdx.z;
    int nrows = z ? g_cnt[z - 1] : T_TOK;
    int m0 = blockIdx.y * 128;
    if (m0 >= nrows) return;
    int n0 = blockIdx.x * 256;

    const __half* aH = g_y1h + (size_t)z * T_TOK * IDIM;
    const __half* bH = g_d2h + (size_t)z * HDIM * IDIM;

    uint32_t sb = smem_u32(smem);

    auto load_stage = [&](int s, int k0) {
        uint32_t base = sb + s * STAGE;
#pragma unroll
        for (int i = 0; i < 6; i++) {
            int cid = tid + i * 256;
            const __half* src;
            uint32_t dst;
            if (cid < 512) {
                int row = cid >> 2, c = cid & 3;
                int r = m0 + row; if (r >= nrows) r = nrows - 1;
                src = aH + (size_t)r * IDIM + k0 + c * 8;
                dst = base + row * PITCHB + c * 16;
            } else {
                int w2 = cid - 512;
                int row = w2 >> 2, c = w2 & 3;
                src = bH + (size_t)(n0 + row) * IDIM + k0 + c * 8;
                dst = base + S_B + row * PITCHB + c * 16;
            }
            cp16(dst, src);
        }
    };

    int l = tid & 31, w = tid >> 5;
    int wm = w & 1, wn = w >> 1;         // warp grid 2m x 4n
    int mW = wm * 64, nW = wn * 64;
    uint32_t aRow = (uint32_t)(l & 15);
    uint32_t aKb  = (uint32_t)(((l >> 4) & 1) * 16);
    uint32_t bRow = (uint32_t)((l & 7) + ((l >> 4) & 1) * 8);
    uint32_t bKb  = (uint32_t)(((l >> 3) & 1) * 16);

    float C[4][8][4] = {};

    for (int s = 0; s < NST - 1; s++) { load_stage(s, s * BK); cp_commit(); }
    const int NIT = IDIM / BK;   // 88
    for (int it = 0; it < NIT; it++) {
        cp_wait<NST - 2>();
        __syncthreads();
        uint32_t base = sb + (it % NST) * STAGE;
#pragma unroll
        for (int ks = 0; ks < 2; ks++) {
            int kb = ks * 32;
            uint32_t ah[4][4];
#pragma unroll
            for (int mt = 0; mt < 4; mt++) {
                uint32_t r = base + (mW + mt * 16 + aRow) * PITCHB + kb + aKb;
                ldmx4(ah[mt], r);
            }
            uint32_t bh[4][4];
#pragma unroll
            for (int p = 0; p < 4; p++) {
                uint32_t r = base + S_B + (nW + p * 16 + bRow) * PITCHB + kb + bKb;
                ldmx4(bh[p], r);
            }
#pragma unroll
            for (int mt = 0; mt < 4; mt++)
#pragma unroll
                for (int nt = 0; nt < 8; nt++) {
                    const uint32_t* bF = &bh[nt >> 1][(nt & 1) * 2];
                    mma16816(C[mt][nt], ah[mt], bF);
                }
        }
        int nl = it + NST - 1;
        if (nl < NIT) load_stage(nl % NST, nl * BK);
        cp_commit();
    }

    float* dstbase = z ? (g_y2 + (size_t)(z - 1) * T_TOK * HDIM) : out;
#pragma unroll
    for (int mt = 0; mt < 4; mt++)
#pragma unroll
        for (int nt = 0; nt < 8; nt++) {
            int mrow = m0 + mW + mt * 16 + (l >> 2);
            int ncol = n0 + nW + nt * 8 + (l & 3) * 2;
#pragma unroll
            for (int h = 0; h < 2; h++) {
                int m = mrow + h * 8;
                if (m < nrows) {
                    float2 v = make_float2(C[mt][nt][2 * h], C[mt][nt][2 * h + 1]);
                    *(float2*)(dstbase + (size_t)m * HDIM + ncol) = v;
                }
            }
        }
}

// ---------------- combine: out[t] += w0*y2[row0] + w1*y2[row1] ----------------
__global__ void combine_kernel(float* __restrict__ out) {
    int t = blockIdx.x;
    int h = threadIdx.x * 4;
    int r0 = g_srow[2 * t],  r1 = g_srow[2 * t + 1];
    float w0 = g_swt[2 * t], w1 = g_swt[2 * t + 1];
    float4 o = *(float4*)(out + (size_t)t * HDIM + h);
    float4 a = *(const float4*)(g_y2 + (size_t)r0 * HDIM + h);
    float4 b = *(const float4*)(g_y2 + (size_t)r1 * HDIM + h);
    o.x += w0 * a.x + w1 * b.x;
    o.y += w0 * a.y + w1 * b.y;
    o.z += w0 * a.z + w1 * b.z;
    o.w += w0 * a.w + w1 * b.w;
    *(float4*)(out + (size_t)t * HDIM + h) = o;
}

// ---------------- launch ----------------
extern "C" void kernel_launch(void* const* d_in, const int* in_sizes, int n_in,
                              void* d_out, int out_size) {
    const float* x    = (const float*)d_in[0];
    const float* wr   = (const float*)d_in[1];
    const float* bias = (const float*)d_in[2];
    const float* sg   = (const float*)d_in[3];
    const float* su   = (const float*)d_in[4];
    const float* sd   = (const float*)d_in[5];
    const float* rg   = (const float*)d_in[6];
    const float* ru   = (const float*)d_in[7];
    const float* rd   = (const float*)d_in[8];
    float* out = (float*)d_out;

    cudaFuncSetAttribute(gemm1_kernel, cudaFuncAttributeMaxDynamicSharedMemorySize, SM_G1);
    cudaFuncSetAttribute(gemm2_kernel, cudaFuncAttributeMaxDynamicSharedMemorySize, SM_G2);

    init_counts_kernel<<<1, 32>>>();
    router_kernel<<<T_TOK / 4, 128>>>(x, wr, bias);
    convx_kernel<<<(T_TOK * HDIM) / 1024, 256>>>(x);
    convT1_kernel<<<dim3(IDIM / 64, HDIM / 32, 16), 256>>>(sg, su, rg, ru);
    convT2_kernel<<<dim3(HDIM / 64, IDIM / 32, 8), 256>>>(sd, rd);

    gemm1_kernel<<<dim3(IDIM / 128, T_TOK / 128, 8), 256, SM_G1>>>();
    gemm2_kernel<<<dim3(HDIM / 256, T_TOK / 128, 8), 256, SM_G2>>>(out);
    combine_kernel<<<T_TOK, HDIM / 4>>>(out);
}